// round 2
// baseline (speedup 1.0000x reference)
#include <cuda_runtime.h>
#include <math.h>
#include <float.h>

#define NROWS   8192
#define IN_DIM  256
#define DIM     128
#define KCODES  8192
#define MBOOK   8
#define EPSBN   1e-5f

// output layout: x_hat [8192,256] ++ res_s [8,8192,128] ++ ce_s [8,8192,128]
#define RES_OFF ((size_t)NROWS * IN_DIM)
#define CE_OFF  (RES_OFF + (size_t)MBOOK * NROWS * DIM)

// scratch (static device allocations only — no cudaMalloc allowed)
__device__ float g_h1[NROWS * 128];
__device__ float g_h2[NROWS * 256];
__device__ float g_ze[NROWS * DIM];
__device__ float g_di[NROWS * DIM];
__device__ float g_t1[NROWS * 256];
__device__ float g_t2[NROWS * 128];
__device__ float g_nn[MBOOK * KCODES];   // ||e||^2 (full, matching reference)

// ---------------------------------------------------------------------------
// Generic tiled GEMM: C = act(bn(A[N,KD] @ W[KD,P] + bias))
// block tile 64x64, 256 threads, micro 4x4
// ---------------------------------------------------------------------------
template<int KD, int P, bool BN, bool RELU>
__global__ void __launch_bounds__(256) gemm_kernel(
    const float* __restrict__ A, const float* __restrict__ W,
    const float* __restrict__ bias,
    const float* __restrict__ gg, const float* __restrict__ be,
    const float* __restrict__ rm, const float* __restrict__ rv,
    float* __restrict__ C)
{
    __shared__ __align__(16) float As[16][68];   // k-major: As[kk][row]
    __shared__ __align__(16) float Ws[16][68];   // k-major: Ws[kk][col]
    const int tid = threadIdx.x;
    const int rid = tid >> 4, cid = tid & 15;
    const int row0 = blockIdx.y * 64, col0 = blockIdx.x * 64;
    float acc[4][4] = {};

    for (int k0 = 0; k0 < KD; k0 += 16) {
        __syncthreads();
        #pragma unroll
        for (int i = 0; i < 4; i++) {
            int idx = tid + i * 256;
            int r  = idx >> 4, kk  = idx & 15;
            As[kk][r] = A[(size_t)(row0 + r) * KD + (k0 + kk)];
            int kk2 = idx >> 6, c  = idx & 63;
            Ws[kk2][c] = W[(size_t)(k0 + kk2) * P + (col0 + c)];
        }
        __syncthreads();
        #pragma unroll
        for (int kk = 0; kk < 16; kk++) {
            float4 a = *(const float4*)&As[kk][rid * 4];
            float4 w = *(const float4*)&Ws[kk][cid * 4];
            float av[4] = {a.x, a.y, a.z, a.w};
            float wv[4] = {w.x, w.y, w.z, w.w};
            #pragma unroll
            for (int r = 0; r < 4; r++)
                #pragma unroll
                for (int c = 0; c < 4; c++)
                    acc[r][c] += av[r] * wv[c];
        }
    }
    #pragma unroll
    for (int r = 0; r < 4; r++) {
        int row = row0 + rid * 4 + r;
        #pragma unroll
        for (int c = 0; c < 4; c++) {
            int col = col0 + cid * 4 + c;
            float v = acc[r][c] + bias[col];
            if constexpr (BN)
                v = (v - rm[col]) / sqrtf(rv[col] + EPSBN) * gg[col] + be[col];
            if constexpr (RELU)
                v = fmaxf(v, 0.0f);
            C[(size_t)row * P + col] = v;
        }
    }
}

// ---------------------------------------------------------------------------
// Precompute ||E_k||^2 for all books/codes
// ---------------------------------------------------------------------------
__global__ void norm_kernel(const float* __restrict__ cbk)
{
    int i = blockIdx.x * 256 + threadIdx.x;           // < MBOOK*KCODES
    const float4* p = (const float4*)(cbk + (size_t)i * DIM);
    float s = 0.f;
    #pragma unroll
    for (int j = 0; j < DIM / 4; j++) {
        float4 q = p[j];
        s += q.x * q.x + q.y * q.y + q.z * q.z + q.w * q.w;
    }
    g_nn[i] = s;
}

// ---------------------------------------------------------------------------
// Persistent residual-VQ kernel. One CTA owns 64 rows for all 8 books.
// Reference-matching score:  d = (||r||^2 - 2 r.e) + ||e||^2  with fp32
// rounding in that association order — d is dominated by ||r||^2 so the
// final rounding (ulp ~1.2e-7) reproduces the reference's tie behavior.
// argmin with strict '<' ascending + lowest-index tie break == jnp.argmin.
// ---------------------------------------------------------------------------
#define VROWS 64
#define VCT   128
#define VKC   16

__global__ void __launch_bounds__(256) vq_kernel(
    const float* __restrict__ ze, const float* __restrict__ cbk,
    float* __restrict__ out)
{
    __shared__ __align__(16) float res_t[DIM][VROWS + 4];  // dim-major residual
    __shared__ __align__(16) float Es[VKC][VCT + 4];       // dim-major E chunk
    __shared__ float rr_s[VROWS];
    __shared__ int bestIdx[VROWS];
    const int tid  = threadIdx.x;
    const int row0 = blockIdx.x * VROWS;
    const int rid  = tid >> 4, cid = tid & 15;
    const int warp = tid >> 5, lane = tid & 31;

    // residual := ze (coalesced gmem read, transposed smem store)
    #pragma unroll
    for (int i = 0; i < (VROWS * DIM) / 256; i++) {
        int idx = tid + i * 256;
        int r = idx >> 7, d = idx & 127;
        res_t[d][r] = ze[(size_t)(row0 + r) * DIM + d];
    }
    __syncthreads();

    for (int m = 0; m < MBOOK; m++) {
        const float* Eb = cbk + (size_t)m * KCODES * DIM;
        const float* nb = g_nn + m * KCODES;

        // emit res_s[m] (residual BEFORE quantization)
        {
            size_t ob = RES_OFF + (size_t)m * NROWS * DIM + (size_t)row0 * DIM;
            #pragma unroll
            for (int i = 0; i < (VROWS * DIM) / 256; i++) {
                int idx = tid + i * 256;
                int r = idx >> 7, d = idx & 127;
                out[ob + (size_t)r * DIM + d] = res_t[d][r];
            }
        }

        // per-row ||r||^2 for this book
        if (tid < VROWS) {
            float s = 0.f;
            #pragma unroll
            for (int d = 0; d < DIM; d++) {
                float v = res_t[d][tid];
                s = fmaf(v, v, s);
            }
            rr_s[tid] = s;
        }
        __syncthreads();

        float rr[4];
        #pragma unroll
        for (int r = 0; r < 4; r++) rr[r] = rr_s[rid * 4 + r];

        float best[4];
        int   bidx[4];
        #pragma unroll
        for (int r = 0; r < 4; r++) { best[r] = FLT_MAX; bidx[r] = 0x7fffffff; }

        for (int cb = 0; cb < KCODES / VCT; cb++) {
            float acc[4][8];
            #pragma unroll
            for (int r = 0; r < 4; r++)
                #pragma unroll
                for (int j = 0; j < 8; j++)
                    acc[r][j] = 0.f;

            #pragma unroll 1
            for (int kc = 0; kc < DIM / VKC; kc++) {
                __syncthreads();
                // stage E[128 codes][16 dims] transposed into smem
                #pragma unroll
                for (int v = 0; v < 2; v++) {
                    int idx = tid * 2 + v;          // < 512 float4s
                    int c = idx >> 2, dg = idx & 3;
                    float4 q = *(const float4*)(Eb + (size_t)(cb * VCT + c) * DIM
                                                + kc * VKC + dg * 4);
                    Es[dg * 4 + 0][c] = q.x;
                    Es[dg * 4 + 1][c] = q.y;
                    Es[dg * 4 + 2][c] = q.z;
                    Es[dg * 4 + 3][c] = q.w;
                }
                __syncthreads();
                #pragma unroll
                for (int kk = 0; kk < VKC; kk++) {
                    float4 a  = *(const float4*)&res_t[kc * VKC + kk][rid * 4];
                    float4 b0 = *(const float4*)&Es[kk][cid * 8];
                    float4 b1 = *(const float4*)&Es[kk][cid * 8 + 4];
                    float av[4] = {a.x, a.y, a.z, a.w};
                    float bv[8] = {b0.x, b0.y, b0.z, b0.w, b1.x, b1.y, b1.z, b1.w};
                    #pragma unroll
                    for (int r = 0; r < 4; r++)
                        #pragma unroll
                        for (int j = 0; j < 8; j++)
                            acc[r][j] += av[r] * bv[j];
                }
            }
            // reference-matching distance: d = (rr - 2*dot) + ee
            #pragma unroll
            for (int j = 0; j < 8; j++) {
                int code = cb * VCT + cid * 8 + j;
                float ee = __ldg(nb + code);
                #pragma unroll
                for (int r = 0; r < 4; r++) {
                    float d1 = rr[r] - 2.0f * acc[r][j];   // fp32 round
                    float d  = d1 + ee;                     // fp32 round
                    if (d < best[r]) { best[r] = d; bidx[r] = code; }
                }
            }
        }

        // reduce argmin over the 16 lanes sharing a row group (tie -> lower idx)
        #pragma unroll
        for (int r = 0; r < 4; r++) {
            float b_ = best[r]; int i_ = bidx[r];
            #pragma unroll
            for (int off = 8; off >= 1; off >>= 1) {
                float ob = __shfl_down_sync(0xffffffffu, b_, off, 16);
                int   oi = __shfl_down_sync(0xffffffffu, i_, off, 16);
                if (ob < b_ || (ob == b_ && oi < i_)) { b_ = ob; i_ = oi; }
            }
            if (cid == 0) bestIdx[rid * 4 + r] = i_;
        }
        __syncthreads();

        // quantize: emit ce_s[m], residual -= ce
        #pragma unroll 1
        for (int rr2 = 0; rr2 < VROWS / 8; rr2++) {
            int row = warp * 8 + rr2;
            int idx = bestIdx[row];
            const float* e = Eb + (size_t)idx * DIM;
            size_t ob = CE_OFF + (size_t)m * NROWS * DIM + (size_t)(row0 + row) * DIM;
            #pragma unroll
            for (int d = lane; d < DIM; d += 32) {
                float cv = __ldg(e + d);
                out[ob + d] = cv;
                res_t[d][row] -= cv;
            }
        }
        __syncthreads();
    }
}

// ---------------------------------------------------------------------------
// di = ze + (sum_m ce_s[m] - ze)   (replicates STE forward rounding)
// ---------------------------------------------------------------------------
__global__ void di_kernel(const float* __restrict__ out)
{
    int i = blockIdx.x * 256 + threadIdx.x;   // < NROWS*DIM
    float zev = g_ze[i];
    float zq = 0.f;
    #pragma unroll
    for (int m = 0; m < MBOOK; m++)
        zq += out[CE_OFF + (size_t)m * NROWS * DIM + i];
    g_di[i] = zev + (zq - zev);
}

// ---------------------------------------------------------------------------
extern "C" void kernel_launch(void* const* d_in, const int* in_sizes, int n_in,
                              void* d_out, int out_size)
{
    const float* x   = (const float*)d_in[0];
    const float* W1  = (const float*)d_in[1];
    const float* b1  = (const float*)d_in[2];
    const float* g1  = (const float*)d_in[3];
    const float* be1 = (const float*)d_in[4];
    const float* rm1 = (const float*)d_in[5];
    const float* rv1 = (const float*)d_in[6];
    const float* W2  = (const float*)d_in[7];
    const float* b2  = (const float*)d_in[8];
    const float* g2  = (const float*)d_in[9];
    const float* be2 = (const float*)d_in[10];
    const float* rm2 = (const float*)d_in[11];
    const float* rv2 = (const float*)d_in[12];
    const float* W3  = (const float*)d_in[13];
    const float* b3  = (const float*)d_in[14];
    const float* cbk = (const float*)d_in[15];
    const float* W4  = (const float*)d_in[16];
    const float* b4  = (const float*)d_in[17];
    const float* g3  = (const float*)d_in[18];
    const float* be3 = (const float*)d_in[19];
    const float* rm3 = (const float*)d_in[20];
    const float* rv3 = (const float*)d_in[21];
    const float* W5  = (const float*)d_in[22];
    const float* b5  = (const float*)d_in[23];
    const float* g4  = (const float*)d_in[24];
    const float* be4 = (const float*)d_in[25];
    const float* rm4 = (const float*)d_in[26];
    const float* rv4 = (const float*)d_in[27];
    const float* W6  = (const float*)d_in[28];
    const float* b6  = (const float*)d_in[29];
    float* out = (float*)d_out;

    float *h1, *h2, *ze, *di, *t1, *t2;
    cudaGetSymbolAddress((void**)&h1, g_h1);
    cudaGetSymbolAddress((void**)&h2, g_h2);
    cudaGetSymbolAddress((void**)&ze, g_ze);
    cudaGetSymbolAddress((void**)&di, g_di);
    cudaGetSymbolAddress((void**)&t1, g_t1);
    cudaGetSymbolAddress((void**)&t2, g_t2);

    // codebook norms (independent of everything else)
    norm_kernel<<<MBOOK * KCODES / 256, 256>>>(cbk);

    // encoder
    gemm_kernel<256, 128, true,  true ><<<dim3(2, 128), 256>>>(x,  W1, b1, g1, be1, rm1, rv1, h1);
    gemm_kernel<128, 256, true,  true ><<<dim3(4, 128), 256>>>(h1, W2, b2, g2, be2, rm2, rv2, h2);
    gemm_kernel<256, 128, false, false><<<dim3(2, 128), 256>>>(h2, W3, b3, nullptr, nullptr, nullptr, nullptr, ze);

    // residual VQ (writes res_s and ce_s directly into d_out)
    vq_kernel<<<NROWS / VROWS, 256>>>(ze, cbk, out);

    // straight-through: di = ze + (zq - ze)
    di_kernel<<<NROWS * DIM / 256, 256>>>(out);

    // decoder
    gemm_kernel<128, 256, true,  true ><<<dim3(4, 128), 256>>>(di, W4, b4, g3, be3, rm3, rv3, t1);
    gemm_kernel<256, 128, true,  true ><<<dim3(2, 128), 256>>>(t1, W5, b5, g4, be4, rm4, rv4, t2);
    gemm_kernel<128, 256, false, false><<<dim3(4, 128), 256>>>(t2, W6, b6, nullptr, nullptr, nullptr, nullptr, out);
}

// round 3
// speedup vs baseline: 1.6368x; 1.6368x over previous
#include <cuda_runtime.h>
#include <math.h>
#include <float.h>
#include <stdint.h>

#define NROWS   8192
#define IN_DIM  256
#define DIM     128
#define KCODES  8192
#define MBOOK   8
#define EPSBN   1e-5f

// output layout: x_hat [8192,256] ++ res_s [8,8192,128] ++ ce_s [8,8192,128]
#define RES_OFF ((size_t)NROWS * IN_DIM)
#define CE_OFF  (RES_OFF + (size_t)MBOOK * NROWS * DIM)

// scratch (static device allocations only — no cudaMalloc allowed)
__device__ float g_h1[NROWS * 128];
__device__ float g_h2[NROWS * 256];
__device__ float g_ze[NROWS * DIM];
__device__ float g_di[NROWS * DIM];
__device__ float g_t1[NROWS * 256];
__device__ float g_t2[NROWS * 128];
__device__ float g_nn[MBOOK * KCODES];   // ||e||^2 (matching reference)

// ---------------------------------------------------------------------------
// packed fp32 pair FMA (sm_100+): d = a*b + d, lanewise, IEEE identical per lane
// ---------------------------------------------------------------------------
__device__ __forceinline__ void ffma2(unsigned long long& d,
                                      unsigned long long a,
                                      unsigned long long b)
{
    asm("fma.rn.f32x2 %0, %1, %2, %0;" : "+l"(d) : "l"(a), "l"(b));
}

// ---------------------------------------------------------------------------
// Generic tiled GEMM: C = act(bn(A[N,KD] @ W[KD,P] + bias))
// ---------------------------------------------------------------------------
template<int KD, int P, bool BN, bool RELU>
__global__ void __launch_bounds__(256) gemm_kernel(
    const float* __restrict__ A, const float* __restrict__ W,
    const float* __restrict__ bias,
    const float* __restrict__ gg, const float* __restrict__ be,
    const float* __restrict__ rm, const float* __restrict__ rv,
    float* __restrict__ C)
{
    __shared__ __align__(16) float As[16][68];
    __shared__ __align__(16) float Ws[16][68];
    const int tid = threadIdx.x;
    const int rid = tid >> 4, cid = tid & 15;
    const int row0 = blockIdx.y * 64, col0 = blockIdx.x * 64;
    float acc[4][4] = {};

    for (int k0 = 0; k0 < KD; k0 += 16) {
        __syncthreads();
        #pragma unroll
        for (int i = 0; i < 4; i++) {
            int idx = tid + i * 256;
            int r  = idx >> 4, kk  = idx & 15;
            As[kk][r] = A[(size_t)(row0 + r) * KD + (k0 + kk)];
            int kk2 = idx >> 6, c  = idx & 63;
            Ws[kk2][c] = W[(size_t)(k0 + kk2) * P + (col0 + c)];
        }
        __syncthreads();
        #pragma unroll
        for (int kk = 0; kk < 16; kk++) {
            float4 a = *(const float4*)&As[kk][rid * 4];
            float4 w = *(const float4*)&Ws[kk][cid * 4];
            float av[4] = {a.x, a.y, a.z, a.w};
            float wv[4] = {w.x, w.y, w.z, w.w};
            #pragma unroll
            for (int r = 0; r < 4; r++)
                #pragma unroll
                for (int c = 0; c < 4; c++)
                    acc[r][c] += av[r] * wv[c];
        }
    }
    #pragma unroll
    for (int r = 0; r < 4; r++) {
        int row = row0 + rid * 4 + r;
        #pragma unroll
        for (int c = 0; c < 4; c++) {
            int col = col0 + cid * 4 + c;
            float v = acc[r][c] + bias[col];
            if constexpr (BN)
                v = (v - rm[col]) / sqrtf(rv[col] + EPSBN) * gg[col] + be[col];
            if constexpr (RELU)
                v = fmaxf(v, 0.0f);
            C[(size_t)row * P + col] = v;
        }
    }
}

// ---------------------------------------------------------------------------
// Precompute ||E_k||^2 for all books/codes
// ---------------------------------------------------------------------------
__global__ void norm_kernel(const float* __restrict__ cbk)
{
    int i = blockIdx.x * 256 + threadIdx.x;
    const float4* p = (const float4*)(cbk + (size_t)i * DIM);
    float s = 0.f;
    #pragma unroll
    for (int j = 0; j < DIM / 4; j++) {
        float4 q = p[j];
        s += q.x * q.x + q.y * q.y + q.z * q.z + q.w * q.w;
    }
    g_nn[i] = s;
}

// ---------------------------------------------------------------------------
// Residual VQ, v3:
//   - E staged code-major into smem via cp.async (double buffered, overlapped)
//   - XOR swizzle (16B units): phys = (code*33 + dq) ^ ((code>>3)&7)
//     -> conflict-free cp.async stores AND conflict-free float4 compute loads
//   - f32x2 packed accumulation over dim-pairs (fold lo+hi at score time)
//   - reference-matching final rounding: d = (rr - 2*dot) + ee
// grid 128 CTAs x 256 thr; CTA tile: 64 rows x (128-code blocks) x all 8 books
// ---------------------------------------------------------------------------
#define VROWS 64
#define VCT   128
#define RES_STRIDE 132                     // floats per res row (33 16B units)
#define ES_UNITS   4224                    // 16B units per E buffer
#define ES_FLOATS  (ES_UNITS * 4)

__device__ __forceinline__ void stageE(float* Ebuf, const float* __restrict__ Eb,
                                       int cb, int tid)
{
    #pragma unroll
    for (int v = 0; v < 16; v++) {
        int f    = v * 256 + tid;
        int code = f >> 5, dq = f & 31;
        int phys = (code * 33 + dq) ^ ((code >> 3) & 7);
        uint32_t dst = (uint32_t)__cvta_generic_to_shared(Ebuf + phys * 4);
        const float* src = Eb + ((size_t)(cb * VCT + code) << 7) + (dq << 2);
        asm volatile("cp.async.cg.shared.global [%0], [%1], 16;"
                     :: "r"(dst), "l"(src));
    }
    asm volatile("cp.async.commit_group;");
}

__global__ void __launch_bounds__(256, 1) vq_kernel(
    const float* __restrict__ ze, const float* __restrict__ cbk,
    float* __restrict__ out)
{
    extern __shared__ float sm[];
    float* res_t   = sm;                                   // [64][132]
    float* Esm     = sm + VROWS * RES_STRIDE;              // 2 x ES_FLOATS
    float* rr_s    = Esm + 2 * ES_FLOATS;                  // [64]
    int*   bestIdx = (int*)(rr_s + VROWS);                 // [64]

    const int tid  = threadIdx.x;
    const int row0 = blockIdx.x * VROWS;
    const int rid  = tid >> 4, cid = tid & 15;
    const int warp = tid >> 5, lane = tid & 31;
    const int swz  = cid & 7;
    int c33[8];
    #pragma unroll
    for (int j = 0; j < 8; j++) c33[j] = (cid * 8 + j) * 33;

    // residual := ze
    #pragma unroll
    for (int i = 0; i < 8; i++) {
        int g = tid + i * 256;
        int r = g >> 5, dq = g & 31;
        *(float4*)(res_t + r * RES_STRIDE + dq * 4) =
            *(const float4*)(ze + (size_t)(row0 + r) * DIM + dq * 4);
    }
    __syncthreads();

    for (int m = 0; m < MBOOK; m++) {
        const float* Eb = cbk + (size_t)m * KCODES * DIM;
        const float* nb = g_nn + m * KCODES;

        // kick off first E tile (async, overlaps with emission + rr below)
        stageE(Esm, Eb, 0, tid);

        // emit res_s[m]
        {
            size_t ob = RES_OFF + (size_t)m * NROWS * DIM + (size_t)row0 * DIM;
            #pragma unroll
            for (int i = 0; i < 8; i++) {
                int g = tid + i * 256;
                int r = g >> 5, dq = g & 31;
                *(float4*)(out + ob + (size_t)r * DIM + dq * 4) =
                    *(const float4*)(res_t + r * RES_STRIDE + dq * 4);
            }
        }

        // per-row ||r||^2, sequential dim order (same as round 2)
        if (tid < VROWS) {
            float s = 0.f;
            #pragma unroll
            for (int dq = 0; dq < 32; dq++) {
                float4 v = *(const float4*)(res_t + tid * RES_STRIDE + dq * 4);
                s = fmaf(v.x, v.x, s); s = fmaf(v.y, v.y, s);
                s = fmaf(v.z, v.z, s); s = fmaf(v.w, v.w, s);
            }
            rr_s[tid] = s;
        }
        __syncthreads();

        float rr[4];
        #pragma unroll
        for (int r = 0; r < 4; r++) rr[r] = rr_s[rid * 4 + r];

        float best[4];
        int   bidx[4];
        #pragma unroll
        for (int r = 0; r < 4; r++) { best[r] = FLT_MAX; bidx[r] = 0x7fffffff; }

        int p = 0;
        for (int cb = 0; cb < KCODES / VCT; cb++) {
            if (cb < KCODES / VCT - 1) {
                stageE(Esm + (p ^ 1) * ES_FLOATS, Eb, cb + 1, tid);
                asm volatile("cp.async.wait_group 1;");
            } else {
                asm volatile("cp.async.wait_group 0;");
            }
            __syncthreads();

            const float* E0 = Esm + p * ES_FLOATS;
            unsigned long long acc[4][8];
            #pragma unroll
            for (int r = 0; r < 4; r++)
                #pragma unroll
                for (int j = 0; j < 8; j++)
                    acc[r][j] = 0ull;

            #pragma unroll 4
            for (int dq = 0; dq < 32; dq++) {
                ulonglong2 a2[4];
                #pragma unroll
                for (int r = 0; r < 4; r++)
                    a2[r] = *(const ulonglong2*)(res_t + (rid * 4 + r) * RES_STRIDE + dq * 4);
                #pragma unroll
                for (int j = 0; j < 8; j++) {
                    int phys = (c33[j] + dq) ^ swz;
                    ulonglong2 b2 = *(const ulonglong2*)(E0 + phys * 4);
                    #pragma unroll
                    for (int r = 0; r < 4; r++) {
                        ffma2(acc[r][j], a2[r].x, b2.x);
                        ffma2(acc[r][j], a2[r].y, b2.y);
                    }
                }
            }

            // scores: d = (rr - 2*dot) + ee, reference rounding structure
            #pragma unroll
            for (int j = 0; j < 8; j++) {
                int code = cb * VCT + cid * 8 + j;
                float ee = __ldg(nb + code);
                #pragma unroll
                for (int r = 0; r < 4; r++) {
                    unsigned long long a = acc[r][j];
                    float dot = __uint_as_float((unsigned)(a & 0xffffffffull))
                              + __uint_as_float((unsigned)(a >> 32));
                    float d1 = rr[r] - 2.0f * dot;
                    float d  = d1 + ee;
                    if (d < best[r]) { best[r] = d; bidx[r] = code; }
                }
            }
            __syncthreads();
            p ^= 1;
        }

        // argmin over the 16 cids of each half-warp (tie -> lower index)
        #pragma unroll
        for (int r = 0; r < 4; r++) {
            float b_ = best[r]; int i_ = bidx[r];
            #pragma unroll
            for (int off = 8; off >= 1; off >>= 1) {
                float ob = __shfl_down_sync(0xffffffffu, b_, off, 16);
                int   oi = __shfl_down_sync(0xffffffffu, i_, off, 16);
                if (ob < b_ || (ob == b_ && oi < i_)) { b_ = ob; i_ = oi; }
            }
            if (cid == 0) bestIdx[rid * 4 + r] = i_;
        }
        __syncthreads();

        // quantize: emit ce_s[m], residual -= ce
        #pragma unroll 1
        for (int rr2 = 0; rr2 < VROWS / 8; rr2++) {
            int row = warp * 8 + rr2;
            int idx = bestIdx[row];
            const float4* e = (const float4*)(Eb + (size_t)idx * DIM);
            size_t ob = CE_OFF + (size_t)m * NROWS * DIM + (size_t)(row0 + row) * DIM;
            float4 cv = __ldg(e + lane);
            *(float4*)(out + ob + lane * 4) = cv;
            float4* rp = (float4*)(res_t + row * RES_STRIDE + lane * 4);
            float4 rv = *rp;
            rv.x -= cv.x; rv.y -= cv.y; rv.z -= cv.z; rv.w -= cv.w;
            *rp = rv;
        }
        __syncthreads();
    }
}

// ---------------------------------------------------------------------------
// di = ze + (sum_m ce_s[m] - ze)
// ---------------------------------------------------------------------------
__global__ void di_kernel(const float* __restrict__ out)
{
    int i = blockIdx.x * 256 + threadIdx.x;
    float zev = g_ze[i];
    float zq = 0.f;
    #pragma unroll
    for (int m = 0; m < MBOOK; m++)
        zq += out[CE_OFF + (size_t)m * NROWS * DIM + i];
    g_di[i] = zev + (zq - zev);
}

// ---------------------------------------------------------------------------
extern "C" void kernel_launch(void* const* d_in, const int* in_sizes, int n_in,
                              void* d_out, int out_size)
{
    const float* x   = (const float*)d_in[0];
    const float* W1  = (const float*)d_in[1];
    const float* b1  = (const float*)d_in[2];
    const float* g1  = (const float*)d_in[3];
    const float* be1 = (const float*)d_in[4];
    const float* rm1 = (const float*)d_in[5];
    const float* rv1 = (const float*)d_in[6];
    const float* W2  = (const float*)d_in[7];
    const float* b2  = (const float*)d_in[8];
    const float* g2  = (const float*)d_in[9];
    const float* be2 = (const float*)d_in[10];
    const float* rm2 = (const float*)d_in[11];
    const float* rv2 = (const float*)d_in[12];
    const float* W3  = (const float*)d_in[13];
    const float* b3  = (const float*)d_in[14];
    const float* cbk = (const float*)d_in[15];
    const float* W4  = (const float*)d_in[16];
    const float* b4  = (const float*)d_in[17];
    const float* g3  = (const float*)d_in[18];
    const float* be3 = (const float*)d_in[19];
    const float* rm3 = (const float*)d_in[20];
    const float* rv3 = (const float*)d_in[21];
    const float* W5  = (const float*)d_in[22];
    const float* b5  = (const float*)d_in[23];
    const float* g4  = (const float*)d_in[24];
    const float* be4 = (const float*)d_in[25];
    const float* rm4 = (const float*)d_in[26];
    const float* rv4 = (const float*)d_in[27];
    const float* W6  = (const float*)d_in[28];
    const float* b6  = (const float*)d_in[29];
    float* out = (float*)d_out;

    float *h1, *h2, *ze, *di, *t1, *t2;
    cudaGetSymbolAddress((void**)&h1, g_h1);
    cudaGetSymbolAddress((void**)&h2, g_h2);
    cudaGetSymbolAddress((void**)&ze, g_ze);
    cudaGetSymbolAddress((void**)&di, g_di);
    cudaGetSymbolAddress((void**)&t1, g_t1);
    cudaGetSymbolAddress((void**)&t2, g_t2);

    const int VQ_SMEM = (VROWS * RES_STRIDE + 2 * ES_FLOATS + VROWS) * 4
                        + VROWS * 4;
    cudaFuncSetAttribute(vq_kernel,
                         cudaFuncAttributeMaxDynamicSharedMemorySize, VQ_SMEM);

    // codebook norms
    norm_kernel<<<MBOOK * KCODES / 256, 256>>>(cbk);

    // encoder
    gemm_kernel<256, 128, true,  true ><<<dim3(2, 128), 256>>>(x,  W1, b1, g1, be1, rm1, rv1, h1);
    gemm_kernel<128, 256, true,  true ><<<dim3(4, 128), 256>>>(h1, W2, b2, g2, be2, rm2, rv2, h2);
    gemm_kernel<256, 128, false, false><<<dim3(2, 128), 256>>>(h2, W3, b3, nullptr, nullptr, nullptr, nullptr, ze);

    // residual VQ (writes res_s and ce_s directly into d_out)
    vq_kernel<<<NROWS / VROWS, 256, VQ_SMEM>>>(ze, cbk, out);

    // straight-through: di = ze + (zq - ze)
    di_kernel<<<NROWS * DIM / 256, 256>>>(out);

    // decoder
    gemm_kernel<128, 256, true,  true ><<<dim3(4, 128), 256>>>(di, W4, b4, g3, be3, rm3, rv3, t1);
    gemm_kernel<256, 128, true,  true ><<<dim3(2, 128), 256>>>(t1, W5, b5, g4, be4, rm4, rv4, t2);
    gemm_kernel<128, 256, false, false><<<dim3(4, 128), 256>>>(t2, W6, b6, nullptr, nullptr, nullptr, nullptr, out);
}